// round 10
// baseline (speedup 1.0000x reference)
#include <cuda_runtime.h>
#include <stdint.h>

// Integrate-and-fire, sequential-equivalent of the reference:
//   per neuron: v=0 at t=0 and t=100; v += x[t]; if (v>2) {spike=1; v=0;}
// in  (4,200,64,64,8):  in[b][t][h1][h2][c],  stride_t=32768
// out (4,200,64,8,64):  out[b][t][h2][c][h1], stride_t=32768
//
// Grid 512 = (b:4, h2:64, chunk:2) x 512 threads (1 neuron/thread, one
// 100-step chunk). 8192 warps / 148 SMs ~= 55 warps/SM (R4 geometry that
// measured occ 79.5%) + R5's packed-byte pipeline:
//   scan role: tid=(h1*8+c) -> coalesced LDG.32, register membrane scan,
//     8 spikes packed as bytes into two uint32 -> 2 STS.32
//     (swizzle word = c*64 + (h1 ^ 4c): conflict-free, h1 warp-aligned).
//   store role: tid=(k4*128 + c*16 + h1q) -> LDS.128 of 4 packed words
//     (h1 = 4*h1q..4*h1q+3), extract byte k4, STG.128 (512B/warp contig).
// 100 steps = 12 full 8-step phases + 4-step tail; double-buffered register
// prefetch (up to 16 loads in flight), one __syncthreads per phase.

#define T_STRIDE 32768

__device__ __forceinline__ float4 unpack4(uint4 a, int sh) {
    float4 f;
    f.x = __uint_as_float(((a.x >> sh) & 1u) * 0x3f800000u);
    f.y = __uint_as_float(((a.y >> sh) & 1u) * 0x3f800000u);
    f.z = __uint_as_float(((a.z >> sh) & 1u) * 0x3f800000u);
    f.w = __uint_as_float(((a.w >> sh) & 1u) * 0x3f800000u);
    return f;
}

#define STEP(W, XV, BIT) do { v += (XV); if (v > 2.0f) { (W) |= (BIT); v = 0.0f; } } while (0)

#define PHASE(CUR, PAR, P) do {                                               \
    uint32_t w0 = 0u, w1 = 0u;                                                \
    STEP(w0, CUR[0], 1u);        STEP(w0, CUR[1], 1u << 8);                   \
    STEP(w0, CUR[2], 1u << 16);  STEP(w0, CUR[3], 1u << 24);                  \
    STEP(w1, CUR[4], 1u);        STEP(w1, CUR[5], 1u << 8);                   \
    STEP(w1, CUR[6], 1u << 16);  STEP(w1, CUR[7], 1u << 24);                  \
    sp[PAR][0][sts] = w0;                                                     \
    sp[PAR][1][sts] = w1;                                                     \
    __syncthreads();                                                          \
    uint4 a0 = *(const uint4*)&sp[PAR][0][lds];                               \
    *(float4*)(outp + (size_t)((P) * 8 + k4) * T_STRIDE) = unpack4(a0, sh);   \
    uint4 a1 = *(const uint4*)&sp[PAR][1][lds];                               \
    *(float4*)(outp + (size_t)((P) * 8 + 4 + k4) * T_STRIDE) = unpack4(a1, sh); \
} while (0)

__global__ __launch_bounds__(512)
void iaf_kernel(const float* __restrict__ in, float* __restrict__ out) {
    const int bid   = blockIdx.x;            // 512 = b(4) x h2(64) x chunk(2)
    const int b     = bid >> 7;
    const int h2    = (bid >> 1) & 63;
    const int chunk = bid & 1;
    const int tid   = threadIdx.x;

    // scan mapping (load-coalesced)
    const int h1_s = tid >> 3;               // 0..63
    const int c_s  = tid & 7;                // 0..7
    // store mapping
    const int k4   = tid >> 7;               // 0..3 (byte within packed word)
    const int c_o  = (tid >> 4) & 7;         // 0..7
    const int h1q  = tid & 15;               // 0..15 (float4 group of h1)

    __shared__ __align__(16) uint32_t sp[2][2][512];

    const size_t tb = (size_t)(b * 200 + chunk * 100) * T_STRIDE;
    const float* inp  = in  + tb + h1_s * 512 + h2 * 8 + c_s;
    float*       outp = out + tb + h2 * 512 + c_o * 64 + h1q * 4;

    const int sts = c_s * 64 + (h1_s ^ (c_s << 2));    // conflict-free STS
    const int lds = c_o * 64 + ((h1q ^ c_o) << 2);     // 16B-aligned LDS.128
    const int sh  = k4 * 8;

    float x0[8], x1[8];

    // prologue: phase 0 -> x0
    #pragma unroll
    for (int k = 0; k < 8; k++) x0[k] = inp[(size_t)k * T_STRIDE];

    float v = 0.0f;

    // 12 full phases = 6 double-iterations; prefetch for p0+2 is guarded
    // (phase 12 is the 4-step tail: only 4 loads valid).
    for (int pp = 0; pp < 6; pp++) {
        const int p0 = 2 * pp;

        {   // prefetch phase p0+1 -> x1 (always full)
            const float* np = inp + (size_t)(p0 + 1) * (8 * T_STRIDE);
            #pragma unroll
            for (int k = 0; k < 8; k++) x1[k] = np[(size_t)k * T_STRIDE];
        }

        PHASE(x0, 0, p0);

        {   // prefetch phase p0+2 -> x0 (tail phase has only 4 steps)
            const float* np = inp + (size_t)(p0 + 2) * (8 * T_STRIDE);
            #pragma unroll
            for (int k = 0; k < 8; k++)
                if (k < 4 || pp < 5) x0[k] = np[(size_t)k * T_STRIDE];
        }

        PHASE(x1, 1, p0 + 1);
    }

    // tail: timesteps 96..99 (phase 12), data in x0[0..3]
    {
        uint32_t w0 = 0u;
        STEP(w0, x0[0], 1u);        STEP(w0, x0[1], 1u << 8);
        STEP(w0, x0[2], 1u << 16);  STEP(w0, x0[3], 1u << 24);
        sp[0][0][sts] = w0;
        __syncthreads();
        uint4 a0 = *(const uint4*)&sp[0][0][lds];
        *(float4*)(outp + (size_t)(96 + k4) * T_STRIDE) = unpack4(a0, sh);
    }
}

extern "C" void kernel_launch(void* const* d_in, const int* in_sizes, int n_in,
                              void* d_out, int out_size) {
    const float* in  = (const float*)d_in[0];
    float*       out = (float*)d_out;
    iaf_kernel<<<512, 512>>>(in, out);
}

// round 12
// speedup vs baseline: 1.1701x; 1.1701x over previous
#include <cuda_runtime.h>
#include <stdint.h>

// Integrate-and-fire, sequential-equivalent of the reference:
//   per neuron: v=0 at t=0 and t=100; v += x[t]; if (v>2) {spike=1; v=0;}
// in  (4,200,64,64,8):  in[b][t][h1][h2][c],  stride_t=32768
// out (4,200,64,8,64):  out[b][t][h2][c][h1], stride_t=32768
//
// Grid 1024 = (b:4, h2:64, chunk:2, h1-half:2) x 256 threads, 1 neuron per
// thread, one 100-step chunk. __launch_bounds__(256,8) caps regs at 32 so
// 8 blocks fit per SM -> capacity 148*8 = 1184 >= 1024: SINGLE WAVE at
// ~55 warps/SM with small 8-warp blocks (best combo from R5/R8/R9 data).
// 100 = 25 exact 4-step phases (no tail, no guards):
//   scan role: tid=(h1l*8+c) -> coalesced LDG.32, register membrane scan,
//     4 spikes packed as bytes into one uint32 -> 1 STS.32
//     (swizzle word = c*32 + (h1l ^ 4c): conflict-free).
//   store role: tid=(k4*64+c*8+h1q) -> LDS.128 of 4 packed words, extract
//     byte k4, STG.128 (fully coalesced 128B segments).
// Double-buffered register prefetch (x0[4]/x1[4]), 1 barrier per phase.

#define T_STRIDE 32768

__device__ __forceinline__ float4 unpack4(uint4 a, int sh) {
    float4 f;
    f.x = __uint_as_float(((a.x >> sh) & 1u) * 0x3f800000u);
    f.y = __uint_as_float(((a.y >> sh) & 1u) * 0x3f800000u);
    f.z = __uint_as_float(((a.z >> sh) & 1u) * 0x3f800000u);
    f.w = __uint_as_float(((a.w >> sh) & 1u) * 0x3f800000u);
    return f;
}

#define STEP(W, XV, BIT) do { v += (XV); if (v > 2.0f) { (W) |= (BIT); v = 0.0f; } } while (0)

// One 4-step phase: pack spikes into one word, stage, transpose-store.
#define PHASE(CUR, PAR, P) do {                                               \
    uint32_t w0 = 0u;                                                         \
    STEP(w0, CUR[0], 1u);        STEP(w0, CUR[1], 1u << 8);                   \
    STEP(w0, CUR[2], 1u << 16);  STEP(w0, CUR[3], 1u << 24);                  \
    sp[PAR][sts] = w0;                                                        \
    __syncthreads();                                                          \
    uint4 a0 = *(const uint4*)&sp[PAR][lds];                                  \
    *(float4*)(outp + (size_t)((P) * 4 + k4) * T_STRIDE) = unpack4(a0, sh);   \
} while (0)

__global__ __launch_bounds__(256, 8)
void iaf_kernel(const float* __restrict__ in, float* __restrict__ out) {
    const int bid   = blockIdx.x;            // 1024 = b(4) x h2(64) x chunk(2) x half(2)
    const int b     = bid >> 8;
    const int h2    = (bid >> 2) & 63;
    const int chunk = (bid >> 1) & 1;
    const int half  = bid & 1;
    const int tid   = threadIdx.x;

    // scan mapping (load-coalesced)
    const int h1l = tid >> 3;                // 0..31 (local h1 within half)
    const int c_s = tid & 7;                 // 0..7
    // store mapping
    const int k4  = tid >> 6;                // 0..3 (byte within packed word)
    const int c_o = (tid >> 3) & 7;          // 0..7
    const int h1q = tid & 7;                 // 0..7 (float4 group within 32 h1)

    __shared__ __align__(16) uint32_t sp[2][256];

    const size_t tb = (size_t)(b * 200 + chunk * 100) * T_STRIDE;
    const float* inp  = in  + tb + (half * 32 + h1l) * 512 + h2 * 8 + c_s;
    float*       outp = out + tb + h2 * 512 + c_o * 64 + half * 32 + h1q * 4;

    const int sts = c_s * 32 + (h1l ^ (c_s << 2));     // conflict-free STS
    const int lds = c_o * 32 + ((h1q ^ c_o) << 2);     // 16B-aligned LDS.128
    const int sh  = k4 * 8;

    float x0[4], x1[4];

    // prologue: phase 0 -> x0
    #pragma unroll
    for (int k = 0; k < 4; k++) x0[k] = inp[(size_t)k * T_STRIDE];

    float v = 0.0f;

    // 25 phases = 12 double-iterations (phases 0..23) + epilogue phase 24.
    // 100 = 25*4 exactly: every prefetch is a full, unconditional 4 loads
    // (p0+2 <= 24 always valid).
    for (int pp = 0; pp < 12; pp++) {
        const int p0 = 2 * pp;

        {   // prefetch phase p0+1 -> x1
            const float* np = inp + (size_t)(p0 + 1) * (4 * T_STRIDE);
            #pragma unroll
            for (int k = 0; k < 4; k++) x1[k] = np[(size_t)k * T_STRIDE];
        }

        PHASE(x0, 0, p0);

        {   // prefetch phase p0+2 -> x0
            const float* np = inp + (size_t)(p0 + 2) * (4 * T_STRIDE);
            #pragma unroll
            for (int k = 0; k < 4; k++) x0[k] = np[(size_t)k * T_STRIDE];
        }

        PHASE(x1, 1, p0 + 1);
    }

    // epilogue: phase 24 (t=96..99 of this chunk), already in x0
    PHASE(x0, 0, 24);
}

extern "C" void kernel_launch(void* const* d_in, const int* in_sizes, int n_in,
                              void* d_out, int out_size) {
    const float* in  = (const float*)d_in[0];
    float*       out = (float*)d_out;
    iaf_kernel<<<1024, 256>>>(in, out);
}